// round 4
// baseline (speedup 1.0000x reference)
#include <cuda_runtime.h>

// Problem constants
#define NC 4
#define NB 128
#define NG 2048
#define NS 32
#define NL 3
#define NBQ 4                 // 128 b-lanes split into 4 groups of 32
#define GPB 32                // g per block in kernel A
#define NWARPS 8
#define GPW (GPB/NWARPS)      // g per warp
#define NTOT (NC*NB*NG)       // 1,048,576
#define BGTOT (NB*NG)         // 262,144 (= 2^18)
#define NIDX (NC*NG*NS*NL)    // 786,432 index entries

// Scratch (no allocation allowed -> device globals)
__device__ float d_Z[NTOT];            // valuation storage (bq layout)
__device__ float d_T[NTOT];            // clause_eval output  (bq layout)
__device__ float d_xq[BGTOT];          // transposed x (bq layout, shared by all c)
__device__ uint4 d_Ip4[NC*NG*12];      // packed uint16 indices: 96 per g = 12 uint4
__device__ unsigned int d_slots[8];    // float-as-uint max accumulators

__device__ __forceinline__ float slot_scale(int idx) {
    if (idx < 0) return 1.0f;
    float m = __uint_as_float(d_slots[idx]);
    return (m > 1.0f) ? (1.0f / m) : 1.0f;
}

// Pack int32 indices (< 2048) into uint16; zero max slots.
__global__ void pack_kernel(const int* __restrict__ I) {
    int i = blockIdx.x * blockDim.x + threadIdx.x;
    if (i < 8) d_slots[i] = 0u;
    if (i < NIDX / 2) {
        int a = I[i * 2], b = I[i * 2 + 1];
        ((unsigned int*)d_Ip4)[i] = (unsigned)a | ((unsigned)b << 16);
    }
}

// Tiled transpose: xq[(bq*NG+g)*32 + lane] = x[(bq*32+lane)*NG + g], coalesced both ways.
__global__ void init_kernel(const float* __restrict__ x) {
    __shared__ float tile[32][33];
    const int g0 = blockIdx.x * 32, bq = blockIdx.y;
    const int lane = threadIdx.x, ty = threadIdx.y;   // block (32, 8)
    #pragma unroll
    for (int r = 0; r < 4; r++) {
        int bl = ty + r * 8;
        tile[bl][lane] = x[(bq * 32 + bl) * NG + g0 + lane];   // coalesced over g
    }
    __syncthreads();
    #pragma unroll
    for (int r = 0; r < 4; r++) {
        int gi = ty + r * 8;
        d_xq[(bq * NG + g0 + gi) * 32 + lane] = tile[lane][gi]; // coalesced over lane
    }
}

// Kernel A: T[c,b,g] = gamma*logsumexp_s( prod_l R[c,b,I[c,g,s,l]] / gamma )
// R = src * scale(scaleIdx);  also atomicMax global max of T into slot maxIdx.
__global__ void __launch_bounds__(256) kernelA(int srcIsZ, int scaleIdx, int maxIdx) {
    __shared__ uint4 sIdx[GPB * 12];      // 32 g * 48 uints = 6KB
    __shared__ float sMax[NWARPS];
    const int c = blockIdx.z, bq = blockIdx.y;
    const int g0 = blockIdx.x * GPB;
    const int tid = threadIdx.x, lane = tid & 31, w = tid >> 5;

    // Stage this block's packed index tile (coalesced uint4) into shared
    const uint4* Ibase = d_Ip4 + (c * NG + g0) * 12;
    #pragma unroll
    for (int i = tid; i < GPB * 12; i += 256) sIdx[i] = Ibase[i];
    __syncthreads();

    const float s = slot_scale(scaleIdx);
    const float s3 = s * s * s;                  // scale folded into 3-way product
    const float inv = s3 * 100.0f;               // (1/gamma) * s3
    const float* __restrict__ slab =
        srcIsZ ? (d_Z + (c * NBQ + bq) * (NG * 32)) : (d_xq + bq * (NG * 32));

    float wmax = 0.0f;
    #pragma unroll 1
    for (int gi = 0; gi < GPW; gi++) {
        const int gl = w * GPW + gi;
        const uint4* ip4 = sIdx + gl * 12;
        float p[NS];
        float amax = 0.0f;                        // products are >= 0
        #pragma unroll
        for (int ch = 0; ch < 4; ch++) {          // 8 substitutions per chunk
            uint4 w0 = ip4[ch * 3 + 0];
            uint4 w1 = ip4[ch * 3 + 1];
            uint4 w2 = ip4[ch * 3 + 2];
            unsigned u[12] = {w0.x, w0.y, w0.z, w0.w,
                              w1.x, w1.y, w1.z, w1.w,
                              w2.x, w2.y, w2.z, w2.w};
            #pragma unroll
            for (int j = 0; j < 8; j++) {
                int k0 = 3 * j, k1 = 3 * j + 1, k2 = 3 * j + 2;
                unsigned i0 = (u[k0 >> 1] >> ((k0 & 1) * 16)) & 0xffffu;
                unsigned i1 = (u[k1 >> 1] >> ((k1 & 1) * 16)) & 0xffffu;
                unsigned i2 = (u[k2 >> 1] >> ((k2 & 1) * 16)) & 0xffffu;
                float v0 = slab[(i0 << 5) + lane];    // 128B warp-coalesced gather
                float v1 = slab[(i1 << 5) + lane];
                float v2 = slab[(i2 << 5) + lane];
                float pp = v0 * v1 * v2;
                p[ch * 8 + j] = pp;
                amax = fmaxf(amax, pp);
            }
        }
        float sum = 0.0f;
        #pragma unroll
        for (int ss = 0; ss < NS; ss++)
            sum += __expf((p[ss] - amax) * inv);
        float t = fmaf(0.01f, __logf(sum), amax * s3);
        d_T[((c * NBQ + bq) * NG + g0 + gl) * 32 + lane] = t;
        wmax = fmaxf(wmax, t);
    }
    #pragma unroll
    for (int o = 16; o; o >>= 1) wmax = fmaxf(wmax, __shfl_xor_sync(0xffffffffu, wmax, o));
    if (lane == 0) sMax[w] = wmax;
    __syncthreads();
    if (tid == 0) {
        float bm = sMax[0];
        #pragma unroll
        for (int k = 1; k < NWARPS; k++) bm = fmaxf(bm, sMax[k]);
        atomicMax(&d_slots[maxIdx], __float_as_uint(bm));
    }
}

// Kernel B: Z = softor2(R, T') elementwise;  R = src*scale(rIdx), T' = T*scale(tIdx).
// atomicMax global max of Z into slot maxIdx.
__global__ void __launch_bounds__(256) kernelB(int srcIsZ, int rIdx, int tIdx, int maxIdx) {
    __shared__ float sMax[8];
    int i = blockIdx.x * 256 + threadIdx.x;
    const float sr = slot_scale(rIdx);
    const float st = slot_scale(tIdx);
    float r = (srcIsZ ? d_Z[i] : d_xq[i & (BGTOT - 1)]) * sr;
    float t = d_T[i] * st;
    float mx = fmaxf(r, t), mn = fminf(r, t);
    float z = fmaf(0.01f, __logf(1.0f + __expf((mn - mx) * 100.0f)), mx);
    d_Z[i] = z;

    float wm = z;
    #pragma unroll
    for (int o = 16; o; o >>= 1) wm = fmaxf(wm, __shfl_xor_sync(0xffffffffu, wm, o));
    int lane = threadIdx.x & 31, w = threadIdx.x >> 5;
    if (lane == 0) sMax[w] = wm;
    __syncthreads();
    if (threadIdx.x == 0) {
        float bm = sMax[0];
        #pragma unroll
        for (int k = 1; k < 8; k++) bm = fmaxf(bm, sMax[k]);
        atomicMax(&d_slots[maxIdx], __float_as_uint(bm));
    }
}

// Final: out[c,b,g] = Z[c,bq,g,lane] * scale(slot5), tiled transpose for coalescing.
__global__ void final_kernel(float* __restrict__ out) {
    __shared__ float tile[32][33];
    const int c = blockIdx.z, bq = blockIdx.y;
    const int g0 = blockIdx.x * 32;
    const int lane = threadIdx.x, ty = threadIdx.y;   // block (32, 8)
    const float sc = slot_scale(5);
    #pragma unroll
    for (int r = 0; r < 4; r++) {
        int gi = ty + r * 8;
        tile[gi][lane] = d_Z[((c * NBQ + bq) * NG + g0 + gi) * 32 + lane];
    }
    __syncthreads();
    #pragma unroll
    for (int r = 0; r < 4; r++) {
        int bl = ty + r * 8;
        out[(c * NB + bq * 32 + bl) * NG + g0 + lane] = tile[lane][bl] * sc;
    }
}

extern "C" void kernel_launch(void* const* d_in, const int* in_sizes, int n_in,
                              void* d_out, int out_size) {
    const float* x = (const float*)d_in[0];
    const int* I = (const int*)d_in[1];
    if (in_sizes[0] != BGTOT) {   // defensive: metadata order swap
        x = (const float*)d_in[1];
        I = (const int*)d_in[0];
    }
    float* out = (float*)d_out;

    pack_kernel<<<(NIDX / 2 + 255) / 256, 256>>>(I);
    init_kernel<<<dim3(NG / 32, NBQ), dim3(32, 8)>>>(x);

    dim3 gA(NG / GPB, NBQ, NC);          // 64 x 4 x 4 = 1024 blocks
    dim3 gB(NTOT / 256);                 // 4096 blocks

    // step 0: R = x (broadcast over c)
    kernelA<<<gA, 256>>>(0, -1, 0);
    kernelB<<<gB, 256>>>(0, -1, 0, 1);
    // step 1
    kernelA<<<gA, 256>>>(1, 1, 2);
    kernelB<<<gB, 256>>>(1, 1, 2, 3);
    // step 2
    kernelA<<<gA, 256>>>(1, 3, 4);
    kernelB<<<gB, 256>>>(1, 3, 4, 5);

    final_kernel<<<dim3(NG / 32, NBQ, NC), dim3(32, 8)>>>(out);
}

// round 5
// speedup vs baseline: 1.1374x; 1.1374x over previous
#include <cuda_runtime.h>

// Problem constants
#define NC 4
#define NB 128
#define NG 2048
#define NS 32
#define NL 3
#define NBQ 4                 // 128 b-lanes split into 4 groups of 32
#define GPB 32                // g per block in kernel A
#define NWARPS 8
#define GPW (GPB/NWARPS)      // g per warp
#define NTOT (NC*NB*NG)       // 1,048,576
#define BGTOT (NB*NG)         // 262,144 (= 2^18)
#define NIDX (NC*NG*NS*NL)    // 786,432 index entries

// Scratch (no allocation allowed -> device globals)
__device__ float d_Z[NTOT];            // valuation storage (bq layout)
__device__ float d_T[NTOT];            // clause_eval output  (bq layout)
__device__ float d_xq[BGTOT];          // transposed x (bq layout, shared by all c)
__device__ uint4 d_Ip4[NC*NG*12];      // packed uint16 indices: 96 per g = 12 uint4
__device__ unsigned int d_slots[8];    // float-as-uint max accumulators

__device__ __forceinline__ float slot_scale(int idx) {
    if (idx < 0) return 1.0f;
    float m = __uint_as_float(d_slots[idx]);
    return (m > 1.0f) ? (1.0f / m) : 1.0f;
}

// Pack int32 indices (< 2048) into uint16; zero max slots.
__global__ void pack_kernel(const int* __restrict__ I) {
    int i = blockIdx.x * blockDim.x + threadIdx.x;
    if (i < 8) d_slots[i] = 0u;
    if (i < NIDX / 2) {
        int a = I[i * 2], b = I[i * 2 + 1];
        ((unsigned int*)d_Ip4)[i] = (unsigned)a | ((unsigned)b << 16);
    }
}

// Tiled transpose: xq[(bq*NG+g)*32 + lane] = x[(bq*32+lane)*NG + g], coalesced both ways.
__global__ void init_kernel(const float* __restrict__ x) {
    __shared__ float tile[32][33];
    const int g0 = blockIdx.x * 32, bq = blockIdx.y;
    const int lane = threadIdx.x, ty = threadIdx.y;   // block (32, 8)
    #pragma unroll
    for (int r = 0; r < 4; r++) {
        int bl = ty + r * 8;
        tile[bl][lane] = x[(bq * 32 + bl) * NG + g0 + lane];   // coalesced over g
    }
    __syncthreads();
    #pragma unroll
    for (int r = 0; r < 4; r++) {
        int gi = ty + r * 8;
        d_xq[(bq * NG + g0 + gi) * 32 + lane] = tile[lane][gi]; // coalesced over lane
    }
}

// Kernel A: T[c,b,g] = gamma*logsumexp_s( prod_l R[c,b,I[c,g,s,l]] / gamma )
// Online (chunked) logsumexp: only 8 products live at a time -> low regs, high occ.
__global__ void __launch_bounds__(256, 6) kernelA(int srcIsZ, int scaleIdx, int maxIdx) {
    __shared__ uint4 sIdx[GPB * 12];      // 32 g * 48 uints = 6KB
    __shared__ float sMax[NWARPS];
    const int c = blockIdx.z, bq = blockIdx.y;
    const int g0 = blockIdx.x * GPB;
    const int tid = threadIdx.x, lane = tid & 31, w = tid >> 5;

    // Stage this block's packed index tile (coalesced uint4) into shared
    const uint4* Ibase = d_Ip4 + (c * NG + g0) * 12;
    #pragma unroll
    for (int i = tid; i < GPB * 12; i += 256) sIdx[i] = Ibase[i];
    __syncthreads();

    const float s = slot_scale(scaleIdx);
    const float s3 = s * s * s;                  // scale folded into 3-way product
    const float c2 = s3 * 144.269504f;           // (1/gamma)*s3*log2(e)
    const float* __restrict__ slab =
        srcIsZ ? (d_Z + (c * NBQ + bq) * (NG * 32)) : (d_xq + bq * (NG * 32));

    float wmax = 0.0f;
    #pragma unroll 1
    for (int gi = 0; gi < GPW; gi++) {
        const int gl = w * GPW + gi;
        const uint4* ip4 = sIdx + gl * 12;
        float m = 0.0f, ssum = 0.0f;             // online LSE state (products >= 0)
        #pragma unroll 1
        for (int ch = 0; ch < 4; ch++) {         // 8 substitutions per chunk
            uint4 w0 = ip4[ch * 3 + 0];
            uint4 w1 = ip4[ch * 3 + 1];
            uint4 w2 = ip4[ch * 3 + 2];
            unsigned u[12] = {w0.x, w0.y, w0.z, w0.w,
                              w1.x, w1.y, w1.z, w1.w,
                              w2.x, w2.y, w2.z, w2.w};
            float p[8];
            float cmax = 0.0f;
            #pragma unroll
            for (int j = 0; j < 8; j++) {
                int k0 = 3 * j, k1 = 3 * j + 1, k2 = 3 * j + 2;
                unsigned i0 = (u[k0 >> 1] >> ((k0 & 1) * 16)) & 0xffffu;
                unsigned i1 = (u[k1 >> 1] >> ((k1 & 1) * 16)) & 0xffffu;
                unsigned i2 = (u[k2 >> 1] >> ((k2 & 1) * 16)) & 0xffffu;
                float v0 = slab[(i0 << 5) + lane];    // 128B warp-coalesced gather
                float v1 = slab[(i1 << 5) + lane];
                float v2 = slab[(i2 << 5) + lane];
                float pp = v0 * v1 * v2;
                p[j] = pp;
                cmax = fmaxf(cmax, pp);
            }
            float mn = fmaxf(m, cmax);
            float acc = ssum * exp2f((m - mn) * c2);
            float e0 = exp2f((p[0] - mn) * c2) + exp2f((p[1] - mn) * c2);
            float e1 = exp2f((p[2] - mn) * c2) + exp2f((p[3] - mn) * c2);
            float e2 = exp2f((p[4] - mn) * c2) + exp2f((p[5] - mn) * c2);
            float e3 = exp2f((p[6] - mn) * c2) + exp2f((p[7] - mn) * c2);
            ssum = acc + ((e0 + e1) + (e2 + e3));
            m = mn;
        }
        float t = fmaf(0.0069314718f, __log2f(ssum), m * s3);   // gamma*ln2*log2
        d_T[((c * NBQ + bq) * NG + g0 + gl) * 32 + lane] = t;
        wmax = fmaxf(wmax, t);
    }
    #pragma unroll
    for (int o = 16; o; o >>= 1) wmax = fmaxf(wmax, __shfl_xor_sync(0xffffffffu, wmax, o));
    if (lane == 0) sMax[w] = wmax;
    __syncthreads();
    if (tid == 0) {
        float bm = sMax[0];
        #pragma unroll
        for (int k = 1; k < NWARPS; k++) bm = fmaxf(bm, sMax[k]);
        atomicMax(&d_slots[maxIdx], __float_as_uint(bm));
    }
}

// Kernel B: Z = softor2(R, T') elementwise, 4 elems/thread via float4.
// R = src*scale(rIdx), T' = T*scale(tIdx); atomicMax global max into slot maxIdx.
__global__ void __launch_bounds__(256) kernelB(int srcIsZ, int rIdx, int tIdx, int maxIdx) {
    __shared__ float sMax[8];
    const int i = blockIdx.x * 256 + threadIdx.x;        // float4 index
    const float sr = slot_scale(rIdx);
    const float st = slot_scale(tIdx);
    float4 rv = srcIsZ ? ((const float4*)d_Z)[i]
                       : ((const float4*)d_xq)[i & (BGTOT / 4 - 1)];
    float4 tv = ((const float4*)d_T)[i];
    float zr[4];
    const float r4[4] = {rv.x, rv.y, rv.z, rv.w};
    const float t4[4] = {tv.x, tv.y, tv.z, tv.w};
    float wm = 0.0f;
    #pragma unroll
    for (int j = 0; j < 4; j++) {
        float r = r4[j] * sr, t = t4[j] * st;
        float mx = fmaxf(r, t), mn = fminf(r, t);
        float z = fmaf(0.0069314718f,
                       __log2f(1.0f + exp2f((mn - mx) * 144.269504f)), mx);
        zr[j] = z;
        wm = fmaxf(wm, z);
    }
    ((float4*)d_Z)[i] = make_float4(zr[0], zr[1], zr[2], zr[3]);

    #pragma unroll
    for (int o = 16; o; o >>= 1) wm = fmaxf(wm, __shfl_xor_sync(0xffffffffu, wm, o));
    int lane = threadIdx.x & 31, w = threadIdx.x >> 5;
    if (lane == 0) sMax[w] = wm;
    __syncthreads();
    if (threadIdx.x == 0) {
        float bm = sMax[0];
        #pragma unroll
        for (int k = 1; k < 8; k++) bm = fmaxf(bm, sMax[k]);
        atomicMax(&d_slots[maxIdx], __float_as_uint(bm));
    }
}

// Final: out[c,b,g] = Z[c,bq,g,lane] * scale(slot5), tiled transpose for coalescing.
__global__ void final_kernel(float* __restrict__ out) {
    __shared__ float tile[32][33];
    const int c = blockIdx.z, bq = blockIdx.y;
    const int g0 = blockIdx.x * 32;
    const int lane = threadIdx.x, ty = threadIdx.y;   // block (32, 8)
    const float sc = slot_scale(5);
    #pragma unroll
    for (int r = 0; r < 4; r++) {
        int gi = ty + r * 8;
        tile[gi][lane] = d_Z[((c * NBQ + bq) * NG + g0 + gi) * 32 + lane];
    }
    __syncthreads();
    #pragma unroll
    for (int r = 0; r < 4; r++) {
        int bl = ty + r * 8;
        out[(c * NB + bq * 32 + bl) * NG + g0 + lane] = tile[lane][bl] * sc;
    }
}

extern "C" void kernel_launch(void* const* d_in, const int* in_sizes, int n_in,
                              void* d_out, int out_size) {
    const float* x = (const float*)d_in[0];
    const int* I = (const int*)d_in[1];
    if (in_sizes[0] != BGTOT) {   // defensive: metadata order swap
        x = (const float*)d_in[1];
        I = (const int*)d_in[0];
    }
    float* out = (float*)d_out;

    pack_kernel<<<(NIDX / 2 + 255) / 256, 256>>>(I);
    init_kernel<<<dim3(NG / 32, NBQ), dim3(32, 8)>>>(x);

    dim3 gA(NG / GPB, NBQ, NC);          // 64 x 4 x 4 = 1024 blocks
    dim3 gB(NTOT / 1024);                // 1024 blocks, 4 elems/thread

    // step 0: R = x (broadcast over c)
    kernelA<<<gA, 256>>>(0, -1, 0);
    kernelB<<<gB, 256>>>(0, -1, 0, 1);
    // step 1
    kernelA<<<gA, 256>>>(1, 1, 2);
    kernelB<<<gB, 256>>>(1, 1, 2, 3);
    // step 2
    kernelA<<<gA, 256>>>(1, 3, 4);
    kernelB<<<gB, 256>>>(1, 3, 4, 5);

    final_kernel<<<dim3(NG / 32, NBQ, NC), dim3(32, 8)>>>(out);
}